// round 3
// baseline (speedup 1.0000x reference)
#include <cuda_runtime.h>
#include <cuda_bf16.h>
#include <stdint.h>
#include <math.h>

#define BATCH 2
#define SEQ   2048
#define DM    1024
#define NH    16
#define DH    64

// Scratch (allocation-free rule: __device__ globals)
__device__ float g_q[BATCH*SEQ*DM];
__device__ float g_k[BATCH*SEQ*DM];
__device__ float g_v[BATCH*SEQ*DM];
__device__ float g_attn[BATCH*SEQ*DM];

// ============================================================================
// Helpers
// ============================================================================
__device__ __forceinline__ uint32_t smem_u32(const void* p) {
    uint32_t a;
    asm("{ .reg .u64 t; cvta.to.shared.u64 t, %1; cvt.u32.u64 %0, t; }"
        : "=r"(a) : "l"(p));
    return a;
}

__device__ __forceinline__ void ldmatrix_x4(uint32_t* r, uint32_t addr) {
    asm volatile("ldmatrix.sync.aligned.m8n8.x4.shared.b16 {%0,%1,%2,%3}, [%4];"
                 : "=r"(r[0]), "=r"(r[1]), "=r"(r[2]), "=r"(r[3]) : "r"(addr));
}

__device__ __forceinline__ void mma_bf16(float* d, const uint32_t* a, const uint32_t* b,
                                         const float* c) {
    asm volatile(
        "mma.sync.aligned.m16n8k16.row.col.f32.bf16.bf16.f32 "
        "{%0,%1,%2,%3}, {%4,%5,%6,%7}, {%8,%9}, {%10,%11,%12,%13};"
        : "=f"(d[0]), "=f"(d[1]), "=f"(d[2]), "=f"(d[3])
        : "r"(a[0]), "r"(a[1]), "r"(a[2]), "r"(a[3]),
          "r"(b[0]), "r"(b[1]),
          "f"(c[0]), "f"(c[1]), "f"(c[2]), "f"(c[3]));
}

// ============================================================================
// Split-bf16 tensor-core GEMM:  C[M,N] = A[M,K] @ W[N,K]^T + bias[N]
// CTA tile 128x128, K-chunk 64, 8 warps (4x2), warp tile 32x64.
// 3 passes (hh + hl + lh) -> fp32-like accuracy.
// ============================================================================
#define GKC    64
#define TSTRB  144                   // bytes per smem row (72 bf16): 16B-aligned, 9*16B -> conflict-free
#define TILE_B (128 * TSTRB)         // 18432 B per tile
#define OFF_AHI 0
#define OFF_ALO (TILE_B)
#define OFF_BHI (2 * TILE_B)
#define OFF_BLO (3 * TILE_B)
#define GEMM_SMEM (4 * TILE_B)       // 73728 B

__device__ __forceinline__ void cvt_store_pair(char* hi_b, char* lo_b,
                                               int row, int c4, float4 v) {
    __nv_bfloat16 h0 = __float2bfloat16(v.x);
    __nv_bfloat16 h1 = __float2bfloat16(v.y);
    __nv_bfloat16 h2 = __float2bfloat16(v.z);
    __nv_bfloat16 h3 = __float2bfloat16(v.w);
    __nv_bfloat16 l0 = __float2bfloat16(v.x - __bfloat162float(h0));
    __nv_bfloat16 l1 = __float2bfloat16(v.y - __bfloat162float(h1));
    __nv_bfloat16 l2 = __float2bfloat16(v.z - __bfloat162float(h2));
    __nv_bfloat16 l3 = __float2bfloat16(v.w - __bfloat162float(h3));
    uint32_t off = (uint32_t)(row * TSTRB + c4 * 8);
    uint2 hp, lp;
    hp.x = (uint32_t)__bfloat16_as_ushort(h0) | ((uint32_t)__bfloat16_as_ushort(h1) << 16);
    hp.y = (uint32_t)__bfloat16_as_ushort(h2) | ((uint32_t)__bfloat16_as_ushort(h3) << 16);
    lp.x = (uint32_t)__bfloat16_as_ushort(l0) | ((uint32_t)__bfloat16_as_ushort(l1) << 16);
    lp.y = (uint32_t)__bfloat16_as_ushort(l2) | ((uint32_t)__bfloat16_as_ushort(l3) << 16);
    *(uint2*)(hi_b + off) = hp;
    *(uint2*)(lo_b + off) = lp;
}

__global__ void __launch_bounds__(256) gemm_tc_kernel(const float* __restrict__ A,
                                                      const float* __restrict__ W,
                                                      const float* __restrict__ bias,
                                                      float* __restrict__ C,
                                                      int M, int N, int K) {
    extern __shared__ char tile[];

    const int tid = threadIdx.x;
    const int wid = tid >> 5;
    const int lane = tid & 31;
    const int m0 = blockIdx.y * 128;
    const int n0 = blockIdx.x * 128;
    const int wm = wid >> 1;          // 0..3 -> warp row tile (32 rows)
    const int wn = wid & 1;           // 0..1 -> warp col tile (64 cols)

    const uint32_t tile_u = smem_u32(tile);

    float acc[2][8][4];
    #pragma unroll
    for (int i = 0; i < 2; i++)
        #pragma unroll
        for (int j = 0; j < 8; j++)
            #pragma unroll
            for (int t = 0; t < 4; t++) acc[i][j][t] = 0.f;

    // per-lane ldmatrix address components (byte offsets within a tile)
    // A x4: lanes 0-15 -> rows 0..15, lanes 16-31 -> same rows, k+8
    const uint32_t a_row = (uint32_t)(wm * 32 + (lane & 15));
    const uint32_t a_kof = (uint32_t)((lane >> 4) * 8) * 2;
    // B x4 (two adjacent n-tiles): lanes 0-7 n0..7@k, 8-15 n0..7@k+8,
    //                              16-23 n8..15@k, 24-31 n8..15@k+8
    const uint32_t b_row = (uint32_t)(wn * 64 + (lane & 7) + ((lane >> 4) & 1) * 8);
    const uint32_t b_kof = (uint32_t)(((lane >> 3) & 1) * 8) * 2;

    const int nchunk = K / GKC;       // 16
    for (int c = 0; c < nchunk; ++c) {
        const int k0 = c * GKC;
        // Prefetch this chunk's gmem data (issued before sync -> overlaps MMA tail)
        float4 ra[8], rb[8];
        #pragma unroll
        for (int i = 0; i < 8; i++) {
            int f4 = tid + i * 256;
            int row = f4 >> 4, c4 = f4 & 15;
            ra[i] = *(const float4*)(A + (size_t)(m0 + row) * K + k0 + c4 * 4);
            rb[i] = *(const float4*)(W + (size_t)(n0 + row) * K + k0 + c4 * 4);
        }
        __syncthreads();   // previous chunk fully consumed
        #pragma unroll
        for (int i = 0; i < 8; i++) {
            int f4 = tid + i * 256;
            int row = f4 >> 4, c4 = f4 & 15;
            cvt_store_pair(tile + OFF_AHI, tile + OFF_ALO, row, c4, ra[i]);
            cvt_store_pair(tile + OFF_BHI, tile + OFF_BLO, row, c4, rb[i]);
        }
        __syncthreads();

        #pragma unroll
        for (int ks = 0; ks < 4; ks++) {
            const uint32_t kbyte = (uint32_t)(ks * 16) * 2;
            uint32_t aHi[2][4], aLo[2][4], bHi[4][4], bLo[4][4];
            #pragma unroll
            for (int mi = 0; mi < 2; mi++) {
                uint32_t ar = tile_u + (a_row + mi * 16) * TSTRB + kbyte + a_kof;
                ldmatrix_x4(aHi[mi], ar + OFF_AHI);
                ldmatrix_x4(aLo[mi], ar + OFF_ALO);
            }
            #pragma unroll
            for (int nt2 = 0; nt2 < 4; nt2++) {
                uint32_t br = tile_u + (b_row + nt2 * 16) * TSTRB + kbyte + b_kof;
                ldmatrix_x4(bHi[nt2], br + OFF_BHI);
                ldmatrix_x4(bLo[nt2], br + OFF_BLO);
            }
            #pragma unroll
            for (int mi = 0; mi < 2; mi++)
                #pragma unroll
                for (int nt = 0; nt < 8; nt++) {
                    const uint32_t* bh = &bHi[nt >> 1][(nt & 1) * 2];
                    const uint32_t* bl = &bLo[nt >> 1][(nt & 1) * 2];
                    mma_bf16(acc[mi][nt], aHi[mi], bh, acc[mi][nt]);  // hh
                    mma_bf16(acc[mi][nt], aHi[mi], bl, acc[mi][nt]);  // hl
                    mma_bf16(acc[mi][nt], aLo[mi], bh, acc[mi][nt]);  // lh
                }
        }
    }

    // Epilogue: acc[mi][nt]: rows m0+wm*32+mi*16+lane/4 (+8), cols n0+wn*64+nt*8+2*(lane&3)
    const int er = lane >> 2;
    const int ec = (lane & 3) * 2;
    #pragma unroll
    for (int mi = 0; mi < 2; mi++) {
        int row0 = m0 + wm * 32 + mi * 16 + er;
        #pragma unroll
        for (int nt = 0; nt < 8; nt++) {
            int col = n0 + wn * 64 + nt * 8 + ec;
            float b0 = __ldg(bias + col), b1 = __ldg(bias + col + 1);
            float2 o0 = make_float2(acc[mi][nt][0] + b0, acc[mi][nt][1] + b1);
            float2 o1 = make_float2(acc[mi][nt][2] + b0, acc[mi][nt][3] + b1);
            *(float2*)(C + (size_t)row0 * N + col) = o0;
            *(float2*)(C + (size_t)(row0 + 8) * N + col) = o1;
        }
    }
}

// ---------------------------------------------------------------------------
// Flash attention (R1 version): one CTA per (b, h, 64-query tile). 256 threads.
// ---------------------------------------------------------------------------
#define SMS 68   // smem row stride (floats)

__global__ void attn_kernel(const float* __restrict__ q,
                            const float* __restrict__ k,
                            const float* __restrict__ v,
                            const int*   __restrict__ mask,
                            float* __restrict__ out) {
    extern __shared__ float smem[];
    float* Qs = smem;                     // [64][68]
    float* Ks = smem + 64 * SMS;          // [64][68]
    float* Vs = smem + 2 * 64 * SMS;      // [64][68]
    float* Mb = smem + 3 * 64 * SMS;      // [64] mask flags (0/1)

    const int b  = blockIdx.z;
    const int h  = blockIdx.y;
    const int q0 = blockIdx.x * 64;
    const int tid = threadIdx.x;
    const int r  = tid >> 2;   // query row within tile
    const int cg = tid & 3;    // column group

    for (int i = tid; i < 64 * DH; i += 256) {
        int row = i >> 6, d = i & 63;
        Qs[row * SMS + d] = q[((size_t)(b * SEQ + q0 + row)) * DM + h * DH + d];
    }

    float m = -1e30f, l = 0.f;
    float acc[16];
    #pragma unroll
    for (int c = 0; c < 16; c++) acc[c] = 0.f;

    for (int j0 = 0; j0 < SEQ; j0 += 64) {
        __syncthreads();
        for (int i = tid; i < 64 * DH; i += 256) {
            int row = i >> 6, d = i & 63;
            size_t gidx = ((size_t)(b * SEQ + j0 + row)) * DM + h * DH + d;
            Ks[row * SMS + d] = k[gidx];
            Vs[row * SMS + d] = v[gidx];
        }
        if (tid < 64) Mb[tid] = (float)mask[b * SEQ + j0 + tid];
        __syncthreads();

        float dotv[16];
        #pragma unroll
        for (int c = 0; c < 16; c++) dotv[c] = 0.f;
        for (int d = 0; d < DH; d++) {
            float qv = Qs[r * SMS + d];
            #pragma unroll
            for (int c = 0; c < 16; c++)
                dotv[c] = fmaf(qv, Ks[(cg + 4 * c) * SMS + d], dotv[c]);
        }

        float tmax = -1e30f;
        #pragma unroll
        for (int c = 0; c < 16; c++) {
            float s = dotv[c] * 0.125f;
            if (Mb[cg + 4 * c] == 0.f) s = -1e9f;
            dotv[c] = s;
            tmax = fmaxf(tmax, s);
        }
        tmax = fmaxf(tmax, __shfl_xor_sync(0xffffffffu, tmax, 1));
        tmax = fmaxf(tmax, __shfl_xor_sync(0xffffffffu, tmax, 2));

        float m_new = fmaxf(m, tmax);
        float alpha = __expf(m - m_new);
        float psum = 0.f;
        #pragma unroll
        for (int c = 0; c < 16; c++) {
            dotv[c] = __expf(dotv[c] - m_new);
            psum += dotv[c];
        }
        psum += __shfl_xor_sync(0xffffffffu, psum, 1);
        psum += __shfl_xor_sync(0xffffffffu, psum, 2);
        l = l * alpha + psum;
        m = m_new;
        #pragma unroll
        for (int c = 0; c < 16; c++) acc[c] *= alpha;

        #pragma unroll 4
        for (int c2 = 0; c2 < 16; c2++) {
            #pragma unroll
            for (int grp = 0; grp < 4; grp++) {
                int col = grp + 4 * c2;
                float p = __shfl_sync(0xffffffffu, dotv[c2], grp, 4);
                #pragma unroll
                for (int cc = 0; cc < 16; cc++)
                    acc[cc] = fmaf(p, Vs[col * SMS + cg + 4 * cc], acc[cc]);
            }
        }
    }

    float inv = 1.f / l;
    #pragma unroll
    for (int c = 0; c < 16; c++)
        out[((size_t)(b * SEQ + q0 + r)) * DM + h * DH + cg + 4 * c] = acc[c] * inv;
}

// ---------------------------------------------------------------------------
extern "C" void kernel_launch(void* const* d_in, const int* in_sizes, int n_in,
                              void* d_out, int out_size) {
    const float* query = (const float*)d_in[0];
    const float* key_t = (const float*)d_in[1];
    const float* value = (const float*)d_in[2];
    const int*   mask  = (const int*)  d_in[3];
    const float* Wq = (const float*)d_in[4];
    const float* bq = (const float*)d_in[5];
    const float* Wk = (const float*)d_in[6];
    const float* bk = (const float*)d_in[7];
    const float* Wv = (const float*)d_in[8];
    const float* bv = (const float*)d_in[9];
    const float* Wo = (const float*)d_in[10];
    const float* bo = (const float*)d_in[11];
    float* out = (float*)d_out;

    float *q, *k, *v, *attn;
    cudaGetSymbolAddress((void**)&q,    g_q);
    cudaGetSymbolAddress((void**)&k,    g_k);
    cudaGetSymbolAddress((void**)&v,    g_v);
    cudaGetSymbolAddress((void**)&attn, g_attn);

    const int M = BATCH * SEQ;       // 4096

    cudaFuncSetAttribute(gemm_tc_kernel,
                         cudaFuncAttributeMaxDynamicSharedMemorySize, GEMM_SMEM);
    const int attn_smem = (3 * 64 * SMS + 64) * (int)sizeof(float);
    cudaFuncSetAttribute(attn_kernel,
                         cudaFuncAttributeMaxDynamicSharedMemorySize, attn_smem);

    dim3 ggrid(DM / 128, M / 128);   // (8, 32)
    gemm_tc_kernel<<<ggrid, 256, GEMM_SMEM>>>(query, Wq, bq, q, M, DM, DM);
    gemm_tc_kernel<<<ggrid, 256, GEMM_SMEM>>>(key_t, Wk, bk, k, M, DM, DM);
    gemm_tc_kernel<<<ggrid, 256, GEMM_SMEM>>>(value, Wv, bv, v, M, DM, DM);

    dim3 agrid(SEQ / 64, NH, BATCH); // (32, 16, 2)
    attn_kernel<<<agrid, 256, attn_smem>>>(q, k, v, mask, attn);

    gemm_tc_kernel<<<ggrid, 256, GEMM_SMEM>>>(attn, Wo, bo, out, M, DM, DM);
}

// round 4
// speedup vs baseline: 4.2733x; 4.2733x over previous
#include <cuda_runtime.h>
#include <cuda_bf16.h>
#include <stdint.h>
#include <math.h>

#define BATCH 2
#define SEQ   2048
#define DM    1024
#define NH    16
#define DH    64

// Scratch (allocation-free rule: __device__ globals)
__device__ float g_q[BATCH*SEQ*DM];
__device__ float g_k[BATCH*SEQ*DM];
__device__ float g_v[BATCH*SEQ*DM];
__device__ float g_attn[BATCH*SEQ*DM];

// ============================================================================
// Helpers
// ============================================================================
__device__ __forceinline__ uint32_t smem_u32(const void* p) {
    uint32_t a;
    asm("{ .reg .u64 t; cvta.to.shared.u64 t, %1; cvt.u32.u64 %0, t; }"
        : "=r"(a) : "l"(p));
    return a;
}

__device__ __forceinline__ void ldmatrix_x4(uint32_t* r, uint32_t addr) {
    asm volatile("ldmatrix.sync.aligned.m8n8.x4.shared.b16 {%0,%1,%2,%3}, [%4];"
                 : "=r"(r[0]), "=r"(r[1]), "=r"(r[2]), "=r"(r[3]) : "r"(addr));
}

__device__ __forceinline__ void ldmatrix_x4_trans(uint32_t* r, uint32_t addr) {
    asm volatile("ldmatrix.sync.aligned.m8n8.x4.trans.shared.b16 {%0,%1,%2,%3}, [%4];"
                 : "=r"(r[0]), "=r"(r[1]), "=r"(r[2]), "=r"(r[3]) : "r"(addr));
}

__device__ __forceinline__ void mma_bf16(float* d, const uint32_t* a, const uint32_t* b,
                                         const float* c) {
    asm volatile(
        "mma.sync.aligned.m16n8k16.row.col.f32.bf16.bf16.f32 "
        "{%0,%1,%2,%3}, {%4,%5,%6,%7}, {%8,%9}, {%10,%11,%12,%13};"
        : "=f"(d[0]), "=f"(d[1]), "=f"(d[2]), "=f"(d[3])
        : "r"(a[0]), "r"(a[1]), "r"(a[2]), "r"(a[3]),
          "r"(b[0]), "r"(b[1]),
          "f"(c[0]), "f"(c[1]), "f"(c[2]), "f"(c[3]));
}

// split one float pair into hi/lo packed bf16x2
__device__ __forceinline__ void pack_hilo(float x, float y, uint32_t& hi, uint32_t& lo) {
    __nv_bfloat16 hx = __float2bfloat16(x);
    __nv_bfloat16 hy = __float2bfloat16(y);
    __nv_bfloat16 lx = __float2bfloat16(x - __bfloat162float(hx));
    __nv_bfloat16 ly = __float2bfloat16(y - __bfloat162float(hy));
    hi = (uint32_t)__bfloat16_as_ushort(hx) | ((uint32_t)__bfloat16_as_ushort(hy) << 16);
    lo = (uint32_t)__bfloat16_as_ushort(lx) | ((uint32_t)__bfloat16_as_ushort(ly) << 16);
}

// ============================================================================
// Split-bf16 tensor-core GEMM (validated R3):  C = A @ W^T + bias
// ============================================================================
#define GKC    64
#define TSTRB  144
#define TILE_B (128 * TSTRB)
#define OFF_AHI 0
#define OFF_ALO (TILE_B)
#define OFF_BHI (2 * TILE_B)
#define OFF_BLO (3 * TILE_B)
#define GEMM_SMEM (4 * TILE_B)

__device__ __forceinline__ void cvt_store_pair(char* hi_b, char* lo_b,
                                               int row, int c4, float4 v) {
    __nv_bfloat16 h0 = __float2bfloat16(v.x);
    __nv_bfloat16 h1 = __float2bfloat16(v.y);
    __nv_bfloat16 h2 = __float2bfloat16(v.z);
    __nv_bfloat16 h3 = __float2bfloat16(v.w);
    __nv_bfloat16 l0 = __float2bfloat16(v.x - __bfloat162float(h0));
    __nv_bfloat16 l1 = __float2bfloat16(v.y - __bfloat162float(h1));
    __nv_bfloat16 l2 = __float2bfloat16(v.z - __bfloat162float(h2));
    __nv_bfloat16 l3 = __float2bfloat16(v.w - __bfloat162float(h3));
    uint32_t off = (uint32_t)(row * TSTRB + c4 * 8);
    uint2 hp, lp;
    hp.x = (uint32_t)__bfloat16_as_ushort(h0) | ((uint32_t)__bfloat16_as_ushort(h1) << 16);
    hp.y = (uint32_t)__bfloat16_as_ushort(h2) | ((uint32_t)__bfloat16_as_ushort(h3) << 16);
    lp.x = (uint32_t)__bfloat16_as_ushort(l0) | ((uint32_t)__bfloat16_as_ushort(l1) << 16);
    lp.y = (uint32_t)__bfloat16_as_ushort(l2) | ((uint32_t)__bfloat16_as_ushort(l3) << 16);
    *(uint2*)(hi_b + off) = hp;
    *(uint2*)(lo_b + off) = lp;
}

__global__ void __launch_bounds__(256) gemm_tc_kernel(const float* __restrict__ A,
                                                      const float* __restrict__ W,
                                                      const float* __restrict__ bias,
                                                      float* __restrict__ C,
                                                      int M, int N, int K) {
    extern __shared__ char tile[];

    const int tid = threadIdx.x;
    const int wid = tid >> 5;
    const int lane = tid & 31;
    const int m0 = blockIdx.y * 128;
    const int n0 = blockIdx.x * 128;
    const int wm = wid >> 1;
    const int wn = wid & 1;

    const uint32_t tile_u = smem_u32(tile);

    float acc[2][8][4];
    #pragma unroll
    for (int i = 0; i < 2; i++)
        #pragma unroll
        for (int j = 0; j < 8; j++)
            #pragma unroll
            for (int t = 0; t < 4; t++) acc[i][j][t] = 0.f;

    const uint32_t a_row = (uint32_t)(wm * 32 + (lane & 15));
    const uint32_t a_kof = (uint32_t)((lane >> 4) * 8) * 2;
    const uint32_t b_row = (uint32_t)(wn * 64 + (lane & 7) + ((lane >> 4) & 1) * 8);
    const uint32_t b_kof = (uint32_t)(((lane >> 3) & 1) * 8) * 2;

    const int nchunk = K / GKC;
    for (int c = 0; c < nchunk; ++c) {
        const int k0 = c * GKC;
        float4 ra[8], rb[8];
        #pragma unroll
        for (int i = 0; i < 8; i++) {
            int f4 = tid + i * 256;
            int row = f4 >> 4, c4 = f4 & 15;
            ra[i] = *(const float4*)(A + (size_t)(m0 + row) * K + k0 + c4 * 4);
            rb[i] = *(const float4*)(W + (size_t)(n0 + row) * K + k0 + c4 * 4);
        }
        __syncthreads();
        #pragma unroll
        for (int i = 0; i < 8; i++) {
            int f4 = tid + i * 256;
            int row = f4 >> 4, c4 = f4 & 15;
            cvt_store_pair(tile + OFF_AHI, tile + OFF_ALO, row, c4, ra[i]);
            cvt_store_pair(tile + OFF_BHI, tile + OFF_BLO, row, c4, rb[i]);
        }
        __syncthreads();

        #pragma unroll
        for (int ks = 0; ks < 4; ks++) {
            const uint32_t kbyte = (uint32_t)(ks * 16) * 2;
            uint32_t aHi[2][4], aLo[2][4], bHi[4][4], bLo[4][4];
            #pragma unroll
            for (int mi = 0; mi < 2; mi++) {
                uint32_t ar = tile_u + (a_row + mi * 16) * TSTRB + kbyte + a_kof;
                ldmatrix_x4(aHi[mi], ar + OFF_AHI);
                ldmatrix_x4(aLo[mi], ar + OFF_ALO);
            }
            #pragma unroll
            for (int nt2 = 0; nt2 < 4; nt2++) {
                uint32_t br = tile_u + (b_row + nt2 * 16) * TSTRB + kbyte + b_kof;
                ldmatrix_x4(bHi[nt2], br + OFF_BHI);
                ldmatrix_x4(bLo[nt2], br + OFF_BLO);
            }
            #pragma unroll
            for (int mi = 0; mi < 2; mi++)
                #pragma unroll
                for (int nt = 0; nt < 8; nt++) {
                    const uint32_t* bh = &bHi[nt >> 1][(nt & 1) * 2];
                    const uint32_t* bl = &bLo[nt >> 1][(nt & 1) * 2];
                    mma_bf16(acc[mi][nt], aHi[mi], bh, acc[mi][nt]);
                    mma_bf16(acc[mi][nt], aHi[mi], bl, acc[mi][nt]);
                    mma_bf16(acc[mi][nt], aLo[mi], bh, acc[mi][nt]);
                }
        }
    }

    const int er = lane >> 2;
    const int ec = (lane & 3) * 2;
    #pragma unroll
    for (int mi = 0; mi < 2; mi++) {
        int row0 = m0 + wm * 32 + mi * 16 + er;
        #pragma unroll
        for (int nt = 0; nt < 8; nt++) {
            int col = n0 + wn * 64 + nt * 8 + ec;
            float b0 = __ldg(bias + col), b1 = __ldg(bias + col + 1);
            float2 o0 = make_float2(acc[mi][nt][0] + b0, acc[mi][nt][1] + b1);
            float2 o1 = make_float2(acc[mi][nt][2] + b0, acc[mi][nt][3] + b1);
            *(float2*)(C + (size_t)row0 * N + col) = o0;
            *(float2*)(C + (size_t)(row0 + 8) * N + col) = o1;
        }
    }
}

// ============================================================================
// Tensor-core flash attention. CTA = (b, h, 128 q-rows). 8 warps x 16 rows.
// KV tile = 64. Split-bf16 3-pass on QK^T and PV.
// smem reuse: phase1 Q hi/lo (2x 128*144) -> main loop K hi/lo + V hi/lo.
// ============================================================================
#define KV_T    64
#define QTILE_B (128 * TSTRB)          // 18432
#define ATT_SMEM (2 * QTILE_B + 256)   // 37120

__global__ void __launch_bounds__(256) attn_tc_kernel(const float* __restrict__ q,
                                                      const float* __restrict__ k,
                                                      const float* __restrict__ v,
                                                      const int*   __restrict__ mask,
                                                      float* __restrict__ out) {
    extern __shared__ char sm[];
    float* msel = (float*)(sm + 2 * QTILE_B);   // 64 mask flags

    const int b  = blockIdx.z;
    const int h  = blockIdx.y;
    const int q0 = blockIdx.x * 128;
    const int tid  = threadIdx.x;
    const int wid  = tid >> 5;
    const int lane = tid & 31;

    const uint32_t u_base = smem_u32(sm);
    const uint32_t u_khi = u_base;                   // 64*144 = 9216
    const uint32_t u_klo = u_base + 9216;
    const uint32_t u_vhi = u_base + 18432;
    const uint32_t u_vlo = u_base + 27648;

    // ---- Phase 1: load Q (scaled by 1/8), split to hi/lo smem, build frags ----
    #pragma unroll
    for (int i = 0; i < 8; i++) {
        int f4 = tid + i * 256;            // 128 rows x 16 float4
        int row = f4 >> 4, c4 = f4 & 15;
        float4 val = *(const float4*)(q + (size_t)(b * SEQ + q0 + row) * DM + h * DH + c4 * 4);
        val.x *= 0.125f; val.y *= 0.125f; val.z *= 0.125f; val.w *= 0.125f;
        cvt_store_pair(sm, sm + QTILE_B, row, c4, val);
    }
    __syncthreads();

    uint32_t qHi[4][4], qLo[4][4];
    {
        const uint32_t qrow = (uint32_t)(wid * 16 + (lane & 15));
        const uint32_t qkof = (uint32_t)((lane >> 4) * 8) * 2;
        #pragma unroll
        for (int ks = 0; ks < 4; ks++) {
            uint32_t addr = u_base + qrow * TSTRB + (uint32_t)(ks * 32) + qkof;
            ldmatrix_x4(qHi[ks], addr);
            ldmatrix_x4(qLo[ks], addr + QTILE_B);
        }
    }
    __syncthreads();   // Q smem now reusable for K/V

    // ---- main loop state ----
    float m0 = -1e30f, m1 = -1e30f, l0 = 0.f, l1 = 0.f;
    float oAcc[8][4];
    #pragma unroll
    for (int nt = 0; nt < 8; nt++)
        #pragma unroll
        for (int t = 0; t < 4; t++) oAcc[nt][t] = 0.f;

    const uint32_t krow_b = (uint32_t)((lane & 7) + ((lane >> 4) & 1) * 8);
    const uint32_t kk_b   = (uint32_t)(((lane >> 3) & 1) * 8) * 2;
    const uint32_t vrow_b = (uint32_t)(lane & 15);
    const uint32_t vcol_b = (uint32_t)(((lane >> 4) & 1) * 8) * 2;
    const int mcol = (lane & 3) * 2;

    for (int j0 = 0; j0 < SEQ; j0 += KV_T) {
        __syncthreads();
        // cooperative K/V load + split (64 rows x 16 float4 each)
        #pragma unroll
        for (int i = 0; i < 4; i++) {
            int f4 = tid + i * 256;
            int row = f4 >> 4, c4 = f4 & 15;
            size_t g = (size_t)(b * SEQ + j0 + row) * DM + h * DH + c4 * 4;
            float4 kv4 = *(const float4*)(k + g);
            float4 vv4 = *(const float4*)(v + g);
            cvt_store_pair((char*)sm, (char*)sm + 9216, row, c4, kv4);
            cvt_store_pair((char*)sm + 18432, (char*)sm + 27648, row, c4, vv4);
        }
        if (tid < KV_T) msel[tid] = (float)mask[b * SEQ + j0 + tid];
        __syncthreads();

        // ---- S = Q @ K^T (3 passes) ----
        float sAcc[8][4];
        #pragma unroll
        for (int nt = 0; nt < 8; nt++)
            #pragma unroll
            for (int t = 0; t < 4; t++) sAcc[nt][t] = 0.f;

        #pragma unroll
        for (int ks = 0; ks < 4; ks++) {
            const uint32_t kbyte = (uint32_t)(ks * 16) * 2;
            uint32_t kH[4][4], kL[4][4];
            #pragma unroll
            for (int nt2 = 0; nt2 < 4; nt2++) {
                uint32_t addr = u_khi + (uint32_t)(nt2 * 16 + krow_b) * TSTRB + kbyte + kk_b;
                ldmatrix_x4(kH[nt2], addr);
                ldmatrix_x4(kL[nt2], addr + 9216);
            }
            #pragma unroll
            for (int nt = 0; nt < 8; nt++) {
                const uint32_t* bh = &kH[nt >> 1][(nt & 1) * 2];
                const uint32_t* bl = &kL[nt >> 1][(nt & 1) * 2];
                mma_bf16(sAcc[nt], qHi[ks], bh, sAcc[nt]);
                mma_bf16(sAcc[nt], qHi[ks], bl, sAcc[nt]);
                mma_bf16(sAcc[nt], qLo[ks], bh, sAcc[nt]);
            }
        }

        // ---- mask + online softmax ----
        float rm0 = -1e30f, rm1 = -1e30f;
        #pragma unroll
        for (int nt = 0; nt < 8; nt++) {
            float2 mf = *(const float2*)(msel + nt * 8 + mcol);
            float s0 = (mf.x != 0.f) ? sAcc[nt][0] : -1e9f;
            float s1 = (mf.y != 0.f) ? sAcc[nt][1] : -1e9f;
            float s2 = (mf.x != 0.f) ? sAcc[nt][2] : -1e9f;
            float s3 = (mf.y != 0.f) ? sAcc[nt][3] : -1e9f;
            sAcc[nt][0] = s0; sAcc[nt][1] = s1; sAcc[nt][2] = s2; sAcc[nt][3] = s3;
            rm0 = fmaxf(rm0, fmaxf(s0, s1));
            rm1 = fmaxf(rm1, fmaxf(s2, s3));
        }
        rm0 = fmaxf(rm0, __shfl_xor_sync(0xffffffffu, rm0, 1));
        rm0 = fmaxf(rm0, __shfl_xor_sync(0xffffffffu, rm0, 2));
        rm1 = fmaxf(rm1, __shfl_xor_sync(0xffffffffu, rm1, 1));
        rm1 = fmaxf(rm1, __shfl_xor_sync(0xffffffffu, rm1, 2));

        float m0n = fmaxf(m0, rm0), m1n = fmaxf(m1, rm1);
        float a0 = __expf(m0 - m0n), a1 = __expf(m1 - m1n);
        float ps0 = 0.f, ps1 = 0.f;
        #pragma unroll
        for (int nt = 0; nt < 8; nt++) {
            float p0 = __expf(sAcc[nt][0] - m0n);
            float p1 = __expf(sAcc[nt][1] - m0n);
            float p2 = __expf(sAcc[nt][2] - m1n);
            float p3 = __expf(sAcc[nt][3] - m1n);
            sAcc[nt][0] = p0; sAcc[nt][1] = p1; sAcc[nt][2] = p2; sAcc[nt][3] = p3;
            ps0 += p0 + p1; ps1 += p2 + p3;
            oAcc[nt][0] *= a0; oAcc[nt][1] *= a0;
            oAcc[nt][2] *= a1; oAcc[nt][3] *= a1;
        }
        ps0 += __shfl_xor_sync(0xffffffffu, ps0, 1);
        ps0 += __shfl_xor_sync(0xffffffffu, ps0, 2);
        ps1 += __shfl_xor_sync(0xffffffffu, ps1, 1);
        ps1 += __shfl_xor_sync(0xffffffffu, ps1, 2);
        l0 = l0 * a0 + ps0;
        l1 = l1 * a1 + ps1;
        m0 = m0n; m1 = m1n;

        // ---- O += P @ V (3 passes) ----
        #pragma unroll
        for (int ks = 0; ks < 4; ks++) {
            // P fragments from S accumulators (tiles 2ks, 2ks+1)
            uint32_t aH[4], aL[4];
            pack_hilo(sAcc[2 * ks][0],     sAcc[2 * ks][1],     aH[0], aL[0]);
            pack_hilo(sAcc[2 * ks][2],     sAcc[2 * ks][3],     aH[1], aL[1]);
            pack_hilo(sAcc[2 * ks + 1][0], sAcc[2 * ks + 1][1], aH[2], aL[2]);
            pack_hilo(sAcc[2 * ks + 1][2], sAcc[2 * ks + 1][3], aH[3], aL[3]);

            uint32_t vH[4][4], vL[4][4];
            #pragma unroll
            for (int nt2 = 0; nt2 < 4; nt2++) {
                uint32_t addr = u_vhi + (uint32_t)(ks * 16 + vrow_b) * TSTRB
                              + (uint32_t)(nt2 * 16) * 2 + vcol_b;
                ldmatrix_x4_trans(vH[nt2], addr);
                ldmatrix_x4_trans(vL[nt2], addr + 9216);
            }
            #pragma unroll
            for (int nt = 0; nt < 8; nt++) {
                const uint32_t* bh = &vH[nt >> 1][(nt & 1) * 2];
                const uint32_t* bl = &vL[nt >> 1][(nt & 1) * 2];
                mma_bf16(oAcc[nt], aH, bh, oAcc[nt]);
                mma_bf16(oAcc[nt], aL, bh, oAcc[nt]);
                mma_bf16(oAcc[nt], aH, bl, oAcc[nt]);
            }
        }
    }

    // ---- epilogue ----
    float i0 = 1.f / l0, i1 = 1.f / l1;
    const int r  = lane >> 2;
    const int c2 = (lane & 3) * 2;
    const int row0 = q0 + wid * 16 + r;
    #pragma unroll
    for (int nt = 0; nt < 8; nt++) {
        int col = h * DH + nt * 8 + c2;
        float2 oA = make_float2(oAcc[nt][0] * i0, oAcc[nt][1] * i0);
        float2 oB = make_float2(oAcc[nt][2] * i1, oAcc[nt][3] * i1);
        *(float2*)(out + (size_t)(b * SEQ + row0) * DM + col) = oA;
        *(float2*)(out + (size_t)(b * SEQ + row0 + 8) * DM + col) = oB;
    }
}

// ---------------------------------------------------------------------------
extern "C" void kernel_launch(void* const* d_in, const int* in_sizes, int n_in,
                              void* d_out, int out_size) {
    const float* query = (const float*)d_in[0];
    const float* key_t = (const float*)d_in[1];
    const float* value = (const float*)d_in[2];
    const int*   mask  = (const int*)  d_in[3];
    const float* Wq = (const float*)d_in[4];
    const float* bq = (const float*)d_in[5];
    const float* Wk = (const float*)d_in[6];
    const float* bk = (const float*)d_in[7];
    const float* Wv = (const float*)d_in[8];
    const float* bv = (const float*)d_in[9];
    const float* Wo = (const float*)d_in[10];
    const float* bo = (const float*)d_in[11];
    float* out = (float*)d_out;

    float *q, *k, *v, *attn;
    cudaGetSymbolAddress((void**)&q,    g_q);
    cudaGetSymbolAddress((void**)&k,    g_k);
    cudaGetSymbolAddress((void**)&v,    g_v);
    cudaGetSymbolAddress((void**)&attn, g_attn);

    const int M = BATCH * SEQ;       // 4096

    cudaFuncSetAttribute(gemm_tc_kernel,
                         cudaFuncAttributeMaxDynamicSharedMemorySize, GEMM_SMEM);
    cudaFuncSetAttribute(attn_tc_kernel,
                         cudaFuncAttributeMaxDynamicSharedMemorySize, ATT_SMEM);

    dim3 ggrid(DM / 128, M / 128);   // (8, 32)
    gemm_tc_kernel<<<ggrid, 256, GEMM_SMEM>>>(query, Wq, bq, q, M, DM, DM);
    gemm_tc_kernel<<<ggrid, 256, GEMM_SMEM>>>(key_t, Wk, bk, k, M, DM, DM);
    gemm_tc_kernel<<<ggrid, 256, GEMM_SMEM>>>(value, Wv, bv, v, M, DM, DM);

    dim3 agrid(SEQ / 128, NH, BATCH); // (16, 16, 2)
    attn_tc_kernel<<<agrid, 256, ATT_SMEM>>>(q, k, v, mask, attn);

    gemm_tc_kernel<<<ggrid, 256, GEMM_SMEM>>>(attn, Wo, bo, out, M, DM, DM);
}